// round 5
// baseline (speedup 1.0000x reference)
#include <cuda_runtime.h>

#define IMG_W  512
#define IMG_H  512
#define IMG_N  (IMG_W * IMG_H)
#define TILE_X 64
#define TILE_Y 64
#define HALO   5
#define NITER  (TILE_Y + 2 * HALO)   /* 74 h-conv rows per tile */
#define ROW_PAD 76
#define MM_BLOCKS 1024
#define MM_THREADS 256

// Normalized 11-tap Gaussian, sigma=1.5, center at ws/2=5.5 (matches ref).
__device__ constexpr float GW[11] = {
    3.2030000e-04f, 2.9556500e-03f, 1.7487670e-02f, 6.6342420e-02f,
    1.6137299e-01f, 2.5168110e-01f, 2.5168110e-01f, 1.6137299e-01f,
    6.6342420e-02f, 1.7487670e-02f, 2.9556500e-03f
};

typedef unsigned long long u64;

__device__ __forceinline__ u64 pack2(float x, float y) {
    u64 r; asm("mov.b64 %0, {%1, %2};" : "=l"(r) : "f"(x), "f"(y)); return r;
}
__device__ __forceinline__ void unpack2(u64 v, float& x, float& y) {
    asm("mov.b64 {%0, %1}, %2;" : "=f"(x), "=f"(y) : "l"(v));
}
__device__ __forceinline__ u64 fma2(u64 a, u64 b, u64 c) {
    u64 d; asm("fma.rn.f32x2 %0, %1, %2, %3;" : "=l"(d) : "l"(a), "l"(b), "l"(c));
    return d;
}
__device__ __forceinline__ u64 mul2(u64 a, u64 b) {
    u64 d; asm("mul.rn.f32x2 %0, %1, %2;" : "=l"(d) : "l"(a), "l"(b));
    return d;
}

// ---------------------------------------------------------------------------
// Global min/max of img1 -> C1, C2 (single kernel, last-block finalize,
// self-resetting counter => graph-replay safe). Fully-unrolled exact-stride
// loop -> 8 front-batched LDG.128 (MLP ~8).
// ---------------------------------------------------------------------------
__device__ float g_blk_max[MM_BLOCKS];
__device__ float g_blk_min[MM_BLOCKS];
__device__ unsigned g_arrive = 0;
__device__ float g_C1, g_C2;

__global__ void __launch_bounds__(MM_THREADS)
minmax_kernel(const float4* __restrict__ x, int n4) {
    float mx = -3.402823466e38f, mn = 3.402823466e38f;
    const int stride = gridDim.x * blockDim.x;
    int i = blockIdx.x * blockDim.x + threadIdx.x;
#pragma unroll 8
    for (; i < n4; i += stride) {
        float4 v = x[i];
        mx = fmaxf(mx, fmaxf(fmaxf(v.x, v.y), fmaxf(v.z, v.w)));
        mn = fminf(mn, fminf(fminf(v.x, v.y), fminf(v.z, v.w)));
    }
#pragma unroll
    for (int o = 16; o > 0; o >>= 1) {
        mx = fmaxf(mx, __shfl_xor_sync(0xFFFFFFFFu, mx, o));
        mn = fminf(mn, __shfl_xor_sync(0xFFFFFFFFu, mn, o));
    }
    __shared__ float smx[8], smn[8];
    __shared__ bool last;
    const int w = threadIdx.x >> 5, l = threadIdx.x & 31;
    if (l == 0) { smx[w] = mx; smn[w] = mn; }
    __syncthreads();
    if (threadIdx.x == 0) {
#pragma unroll
        for (int k = 1; k < MM_THREADS / 32; ++k) {
            mx = fmaxf(mx, smx[k]); mn = fminf(mn, smn[k]);
        }
        g_blk_max[blockIdx.x] = mx;
        g_blk_min[blockIdx.x] = mn;
        __threadfence();
        last = (atomicAdd(&g_arrive, 1u) == (unsigned)(gridDim.x - 1));
    }
    __syncthreads();
    if (last) {
        float fx = -3.402823466e38f, fn = 3.402823466e38f;
#pragma unroll
        for (int k = 0; k < MM_BLOCKS / MM_THREADS; ++k) {
            fx = fmaxf(fx, g_blk_max[threadIdx.x + k * MM_THREADS]);
            fn = fminf(fn, g_blk_min[threadIdx.x + k * MM_THREADS]);
        }
#pragma unroll
        for (int o = 16; o > 0; o >>= 1) {
            fx = fmaxf(fx, __shfl_xor_sync(0xFFFFFFFFu, fx, o));
            fn = fminf(fn, __shfl_xor_sync(0xFFFFFFFFu, fn, o));
        }
        if (l == 0) { smx[w] = fx; smn[w] = fn; }
        __syncthreads();
        if (threadIdx.x == 0) {
#pragma unroll
            for (int k = 1; k < MM_THREADS / 32; ++k) {
                fx = fmaxf(fx, smx[k]); fn = fminf(fn, smn[k]);
            }
            float L = fx - fn;
            if (L == 0.f) L = 5.f;
            g_C1 = (0.01f * L) * (0.01f * L);
            g_C2 = (0.03f * L) * (0.03f * L);
            g_arrive = 0;
        }
    }
}

// ---------------------------------------------------------------------------
// Fused separable-SSIM kernel: 64x64 tiles, 64 threads (10 CTAs/SM),
// pair-batched rows, ab precomputed in smem, packed f32x2 datapath
// ---------------------------------------------------------------------------
__device__ __forceinline__ void load_row(const float* __restrict__ p1,
                                         const float* __restrict__ p2,
                                         int hy, int x0, int tx,
                                         float2& va, float2& vb) {
    va = make_float2(0.f, 0.f);
    vb = make_float2(0.f, 0.f);
    if ((unsigned)hy < (unsigned)IMG_H) {
        const int r = hy * IMG_W;
        const int cA = x0 - HALO + tx;
        if ((unsigned)cA < (unsigned)IMG_W)
            va = make_float2(__ldg(p1 + r + cA), __ldg(p2 + r + cA));
        const int cB = cA + TILE_X;
        if (tx < 2 * HALO && (unsigned)cB < (unsigned)IMG_W)
            vb = make_float2(__ldg(p1 + r + cB), __ldg(p2 + r + cB));
    }
}

__global__ void __launch_bounds__(TILE_X, 10)
ssim_kernel(const float* __restrict__ img1, const float* __restrict__ img2,
            float* __restrict__ out) {
    const int tx = threadIdx.x;
    const int x0 = blockIdx.x * TILE_X;
    const int y0 = blockIdx.y * TILE_Y;
    const long imgoff = (long)blockIdx.z * IMG_N;
    const float* p1 = img1 + imgoff;
    const float* p2 = img2 + imgoff;
    float* po = out + imgoff;

    const float C1 = g_C1;
    const float C2 = g_C2;

    // two alternating buffer-sets, each holding a PAIR of rows
    __shared__ u64   sab[2][2][ROW_PAD];   // (img1, img2) packed per column
    __shared__ float sp [2][2][ROW_PAD];   // a*b per column

    // packed tap weights (6 distinct, symmetric)
    u64 WW6[6];
#pragma unroll
    for (int k = 0; k < 6; ++k) WW6[k] = pack2(GW[k], GW[k]);

    // vertical rolling ring: packed (mu1,mu2), packed (x2,y2), scalar xy
    u64 rm12[11], r1122[11];
    float r12[11];
#pragma unroll
    for (int k = 0; k < 11; ++k) { rm12[k] = 0ull; r1122[k] = 0ull; r12[k] = 0.f; }

    float2 A0, B0, A1, B1;
    load_row(p1, p2, y0 - HALO,     x0, tx, A0, B0);
    load_row(p1, p2, y0 - HALO + 1, x0, tx, A1, B1);
    int bs = 0;

#define HPASS(SLOT, RR)                                                        \
    do {                                                                       \
        u64 h01 = 0ull, h23 = 0ull; float h4 = 0.f;                            \
        _Pragma("unroll")                                                      \
        for (int k = 0; k < 11; ++k) {                                         \
            const int kk = (k <= 5) ? k : (11 - k);                            \
            const u64 p  = sab[bs][RR][tx + k];                                \
            const float ab = sp[bs][RR][tx + k];                               \
            h01 = fma2(p, WW6[kk], h01);                                       \
            h23 = fma2(mul2(p, p), WW6[kk], h23);                              \
            h4  = fmaf(ab, GW[k], h4);                                         \
        }                                                                      \
        rm12[SLOT] = h01; r1122[SLOT] = h23; r12[SLOT] = h4;                   \
    } while (0)

#define VPASS(SLOT, ROW)                                                       \
    do {                                                                       \
        u64 M = 0ull, S = 0ull; float s12 = 0.f;                               \
        _Pragma("unroll")                                                      \
        for (int k = 0; k < 11; ++k) {                                         \
            const int s  = ((SLOT) + 1 + k) % 11;                              \
            const int kk = (k <= 5) ? k : (11 - k);                            \
            M   = fma2(rm12[s],  WW6[kk], M);                                  \
            S   = fma2(r1122[s], WW6[kk], S);                                  \
            s12 = fmaf(r12[s], GW[k], s12);                                    \
        }                                                                      \
        float mu1, mu2, e11, e22;                                              \
        unpack2(M, mu1, mu2); unpack2(S, e11, e22);                            \
        const float mu1sq = mu1 * mu1;                                         \
        const float mu2sq = mu2 * mu2;                                         \
        const float mu12  = mu1 * mu2;                                         \
        const float num = fmaf(2.f, mu12, C1) * fmaf(2.f, s12 - mu12, C2);     \
        const float den = (mu1sq + mu2sq + C1) *                               \
                          ((e11 - mu1sq) + (e22 - mu2sq) + C2);                \
        po[(y0 + (ROW) - 2 * HALO) * IMG_W + x0 + tx] = __fdividef(num, den);  \
    } while (0)

    for (int ib = 0; ib < NITER; ib += 22) {
#pragma unroll
        for (int jj = 0; jj < 11; ++jj) {
            const int i0 = ib + 2 * jj;
            if (i0 < NITER) {
                // publish prefetched pair (values + a*b products)
                sab[bs][0][tx] = pack2(A0.x, A0.y);
                sp [bs][0][tx] = A0.x * A0.y;
                sab[bs][1][tx] = pack2(A1.x, A1.y);
                sp [bs][1][tx] = A1.x * A1.y;
                if (tx < 2 * HALO) {
                    sab[bs][0][TILE_X + tx] = pack2(B0.x, B0.y);
                    sp [bs][0][TILE_X + tx] = B0.x * B0.y;
                    sab[bs][1][TILE_X + tx] = pack2(B1.x, B1.y);
                    sp [bs][1][TILE_X + tx] = B1.x * B1.y;
                }
                // prefetch next pair (overlaps with compute after the sync)
                load_row(p1, p2, y0 - HALO + i0 + 2, x0, tx, A0, B0);
                load_row(p1, p2, y0 - HALO + i0 + 3, x0, tx, A1, B1);
                __syncthreads();

                const int s0 = (2 * jj) % 11;       // compile-time
                const int s1 = (2 * jj + 1) % 11;   // compile-time
                HPASS(s0, 0);
                if (i0 >= 2 * HALO) VPASS(s0, i0);
                HPASS(s1, 1);
                if (i0 >= 2 * HALO) VPASS(s1, i0 + 1);
                bs ^= 1;
            }
        }
    }
#undef HPASS
#undef VPASS
}

// ---------------------------------------------------------------------------
extern "C" void kernel_launch(void* const* d_in, const int* in_sizes, int n_in,
                              void* d_out, int out_size) {
    const float* img1 = (const float*)d_in[0];
    const float* img2 = (const float*)d_in[1];
    float* out = (float*)d_out;
    const int n = in_sizes[0];                 // 32*1*512*512 = 8388608

    minmax_kernel<<<MM_BLOCKS, MM_THREADS>>>((const float4*)img1, n / 4);

    dim3 grid(IMG_W / TILE_X, IMG_H / TILE_Y, n / IMG_N);   // (8, 8, 32)
    ssim_kernel<<<grid, TILE_X>>>(img1, img2, out);
}

// round 6
// speedup vs baseline: 1.1253x; 1.1253x over previous
#include <cuda_runtime.h>

#define IMG_W  512
#define IMG_H  512
#define IMG_N  (IMG_W * IMG_H)
#define TILE_X 128            /* output columns per CTA */
#define NT     64             /* threads; each owns 2 adjacent columns */
#define TILE_Y 64
#define HALO   5
#define NITER  (TILE_Y + 2 * HALO)   /* 74 h-conv rows per tile */
#define ROW_E  140            /* smem row entries: cols x0-6 .. x0+133 */
#define MM_BLOCKS 1024
#define MM_THREADS 256

// Normalized 11-tap Gaussian, sigma=1.5, center at ws/2=5.5 (matches ref).
__device__ constexpr float GW[11] = {
    3.2030000e-04f, 2.9556500e-03f, 1.7487670e-02f, 6.6342420e-02f,
    1.6137299e-01f, 2.5168110e-01f, 2.5168110e-01f, 1.6137299e-01f,
    6.6342420e-02f, 1.7487670e-02f, 2.9556500e-03f
};

typedef unsigned long long u64;

__device__ __forceinline__ u64 pack2(float x, float y) {
    u64 r; asm("mov.b64 %0, {%1, %2};" : "=l"(r) : "f"(x), "f"(y)); return r;
}
__device__ __forceinline__ void unpack2(u64 v, float& x, float& y) {
    asm("mov.b64 {%0, %1}, %2;" : "=f"(x), "=f"(y) : "l"(v));
}
__device__ __forceinline__ u64 fma2(u64 a, u64 b, u64 c) {
    u64 d; asm("fma.rn.f32x2 %0, %1, %2, %3;" : "=l"(d) : "l"(a), "l"(b), "l"(c));
    return d;
}
__device__ __forceinline__ u64 mul2(u64 a, u64 b) {
    u64 d; asm("mul.rn.f32x2 %0, %1, %2;" : "=l"(d) : "l"(a), "l"(b));
    return d;
}

// ---------------------------------------------------------------------------
// Global min/max of img1 -> C1, C2 (single kernel, last-block finalize,
// self-resetting counter => graph-replay safe)
// ---------------------------------------------------------------------------
__device__ float g_blk_max[MM_BLOCKS];
__device__ float g_blk_min[MM_BLOCKS];
__device__ unsigned g_arrive = 0;
__device__ float g_C1, g_C2;

__global__ void __launch_bounds__(MM_THREADS)
minmax_kernel(const float4* __restrict__ x, int n4) {
    float mx = -3.402823466e38f, mn = 3.402823466e38f;
    const int stride = gridDim.x * blockDim.x;
    int i = blockIdx.x * blockDim.x + threadIdx.x;
#pragma unroll 8
    for (; i < n4; i += stride) {
        float4 v = x[i];
        mx = fmaxf(mx, fmaxf(fmaxf(v.x, v.y), fmaxf(v.z, v.w)));
        mn = fminf(mn, fminf(fminf(v.x, v.y), fminf(v.z, v.w)));
    }
#pragma unroll
    for (int o = 16; o > 0; o >>= 1) {
        mx = fmaxf(mx, __shfl_xor_sync(0xFFFFFFFFu, mx, o));
        mn = fminf(mn, __shfl_xor_sync(0xFFFFFFFFu, mn, o));
    }
    __shared__ float smx[8], smn[8];
    __shared__ bool last;
    const int w = threadIdx.x >> 5, l = threadIdx.x & 31;
    if (l == 0) { smx[w] = mx; smn[w] = mn; }
    __syncthreads();
    if (threadIdx.x == 0) {
#pragma unroll
        for (int k = 1; k < MM_THREADS / 32; ++k) {
            mx = fmaxf(mx, smx[k]); mn = fminf(mn, smn[k]);
        }
        g_blk_max[blockIdx.x] = mx;
        g_blk_min[blockIdx.x] = mn;
        __threadfence();
        last = (atomicAdd(&g_arrive, 1u) == (unsigned)(gridDim.x - 1));
    }
    __syncthreads();
    if (last) {
        float fx = -3.402823466e38f, fn = 3.402823466e38f;
#pragma unroll
        for (int k = 0; k < MM_BLOCKS / MM_THREADS; ++k) {
            fx = fmaxf(fx, g_blk_max[threadIdx.x + k * MM_THREADS]);
            fn = fminf(fn, g_blk_min[threadIdx.x + k * MM_THREADS]);
        }
#pragma unroll
        for (int o = 16; o > 0; o >>= 1) {
            fx = fmaxf(fx, __shfl_xor_sync(0xFFFFFFFFu, fx, o));
            fn = fminf(fn, __shfl_xor_sync(0xFFFFFFFFu, fn, o));
        }
        if (l == 0) { smx[w] = fx; smn[w] = fn; }
        __syncthreads();
        if (threadIdx.x == 0) {
#pragma unroll
            for (int k = 1; k < MM_THREADS / 32; ++k) {
                fx = fmaxf(fx, smx[k]); fn = fminf(fn, smn[k]);
            }
            float L = fx - fn;
            if (L == 0.f) L = 5.f;
            g_C1 = (0.01f * L) * (0.01f * L);
            g_C2 = (0.03f * L) * (0.03f * L);
            g_arrive = 0;
        }
    }
}

// ---------------------------------------------------------------------------
// Fused separable-SSIM: 2 px/thread, tap-window sharing, packed f32x2,
// pair-batched rows, vectorized gmem I/O
// ---------------------------------------------------------------------------
// One row of inputs for this thread: interior pair + (tx<6) halo pair.
struct RowLd { float2 i1, i2, h1, h2; };

__device__ __forceinline__ RowLd load_row(const float* __restrict__ p1,
                                          const float* __restrict__ p2,
                                          int hy, int x0, int tx) {
    RowLd r;
    r.i1 = make_float2(0.f, 0.f); r.i2 = r.i1; r.h1 = r.i1; r.h2 = r.i1;
    if ((unsigned)hy < (unsigned)IMG_H) {
        const int base = hy * IMG_W;
        const int cI = x0 - 6 + 2 * tx;              // even -> aligned float2
        if ((unsigned)cI < (unsigned)IMG_W) {
            r.i1 = *(const float2*)(p1 + base + cI);
            r.i2 = *(const float2*)(p2 + base + cI);
        }
        if (tx < 6) {
            const int cH = cI + TILE_X;              // j = 128 + 2tx
            if ((unsigned)cH < (unsigned)IMG_W) {
                r.h1 = *(const float2*)(p1 + base + cH);
                r.h2 = *(const float2*)(p2 + base + cH);
            }
        }
    }
    return r;
}

__global__ void __launch_bounds__(NT)
ssim_kernel(const float* __restrict__ img1, const float* __restrict__ img2,
            float* __restrict__ out) {
    const int tx = threadIdx.x;
    const int x0 = blockIdx.x * TILE_X;
    const int y0 = blockIdx.y * TILE_Y;
    const long imgoff = (long)blockIdx.z * IMG_N;
    const float* p1 = img1 + imgoff;
    const float* p2 = img2 + imgoff;
    float* po = out + imgoff;

    const float C1 = g_C1;
    const float C2 = g_C2;

    // two alternating buffer-sets, each a PAIR of rows.
    // entry j <-> image col x0-6+j, j = 0..139
    __shared__ u64   spab[2][2][ROW_E];   // (img1, img2) packed
    __shared__ float sab [2][2][ROW_E];   // img1*img2

    u64 WW6[6];
#pragma unroll
    for (int k = 0; k < 6; ++k) WW6[k] = pack2(GW[k], GW[k]);

    // per-pixel vertical rings (2 pixels per thread)
    u64 rm12[2][11], r1122[2][11];
    float r12[2][11];
#pragma unroll
    for (int k = 0; k < 11; ++k) {
        rm12[0][k] = 0ull; rm12[1][k] = 0ull;
        r1122[0][k] = 0ull; r1122[1][k] = 0ull;
        r12[0][k] = 0.f; r12[1][k] = 0.f;
    }

    RowLd R0 = load_row(p1, p2, y0 - HALO,     x0, tx);
    RowLd R1 = load_row(p1, p2, y0 - HALO + 1, x0, tx);
    int bs = 0;

    // h-pass for BOTH pixels of this thread, row RR of buffer set bs.
    // taps for px0 at smem j=2tx+1..2tx+11, px1 at 2tx+2..2tx+12.
#define HPASS2(SLOT, RR)                                                       \
    do {                                                                       \
        const int jb = 2 * tx + 1;                                             \
        u64 p_[12]; float ab_[12];                                             \
        _Pragma("unroll")                                                      \
        for (int t = 0; t < 12; ++t) { p_[t] = spab[bs][RR][jb + t];           \
                                       ab_[t] = sab[bs][RR][jb + t]; }         \
        u64 pp_[12];                                                           \
        _Pragma("unroll")                                                      \
        for (int t = 0; t < 12; ++t) pp_[t] = mul2(p_[t], p_[t]);              \
        u64 hA01 = 0ull, hA23 = 0ull, hB01 = 0ull, hB23 = 0ull;                \
        float hA4 = 0.f, hB4 = 0.f;                                            \
        _Pragma("unroll")                                                      \
        for (int k = 0; k < 11; ++k) {                                         \
            const int kk = (k <= 5) ? k : (11 - k);                            \
            hA01 = fma2(p_[k],      WW6[kk], hA01);                            \
            hA23 = fma2(pp_[k],     WW6[kk], hA23);                            \
            hA4  = fmaf(ab_[k],     GW[k],   hA4);                             \
            hB01 = fma2(p_[k + 1],  WW6[kk], hB01);                            \
            hB23 = fma2(pp_[k + 1], WW6[kk], hB23);                            \
            hB4  = fmaf(ab_[k + 1], GW[k],   hB4);                             \
        }                                                                      \
        rm12[0][SLOT] = hA01; r1122[0][SLOT] = hA23; r12[0][SLOT] = hA4;       \
        rm12[1][SLOT] = hB01; r1122[1][SLOT] = hB23; r12[1][SLOT] = hB4;       \
    } while (0)

#define VPX(PX, SLOT, RES)                                                     \
    do {                                                                       \
        u64 M = 0ull, S = 0ull; float s12 = 0.f;                               \
        _Pragma("unroll")                                                      \
        for (int k = 0; k < 11; ++k) {                                         \
            const int s  = ((SLOT) + 1 + k) % 11;                              \
            const int kk = (k <= 5) ? k : (11 - k);                            \
            M   = fma2(rm12[PX][s],  WW6[kk], M);                              \
            S   = fma2(r1122[PX][s], WW6[kk], S);                              \
            s12 = fmaf(r12[PX][s], GW[k], s12);                                \
        }                                                                      \
        float mu1, mu2, e11, e22;                                              \
        unpack2(M, mu1, mu2); unpack2(S, e11, e22);                            \
        const float mu1sq = mu1 * mu1;                                         \
        const float mu2sq = mu2 * mu2;                                         \
        const float mu12  = mu1 * mu2;                                         \
        const float num = fmaf(2.f, mu12, C1) * fmaf(2.f, s12 - mu12, C2);     \
        const float den = (mu1sq + mu2sq + C1) *                               \
                          ((e11 - mu1sq) + (e22 - mu2sq) + C2);                \
        RES = __fdividef(num, den);                                            \
    } while (0)

#define VPASS2(SLOT, ROW)                                                      \
    do {                                                                       \
        float2 res;                                                            \
        VPX(0, SLOT, res.x);                                                   \
        VPX(1, SLOT, res.y);                                                   \
        *(float2*)(po + (y0 + (ROW) - 2 * HALO) * IMG_W + x0 + 2 * tx) = res;  \
    } while (0)

#define PUBLISH(RR, RL)                                                        \
    do {                                                                       \
        ulonglong2 q;                                                          \
        q.x = pack2((RL).i1.x, (RL).i2.x);                                     \
        q.y = pack2((RL).i1.y, (RL).i2.y);                                     \
        *(ulonglong2*)&spab[bs][RR][2 * tx] = q;                               \
        *(float2*)&sab[bs][RR][2 * tx] =                                       \
            make_float2((RL).i1.x * (RL).i2.x, (RL).i1.y * (RL).i2.y);         \
        if (tx < 6) {                                                          \
            ulonglong2 qh;                                                     \
            qh.x = pack2((RL).h1.x, (RL).h2.x);                                \
            qh.y = pack2((RL).h1.y, (RL).h2.y);                                \
            *(ulonglong2*)&spab[bs][RR][TILE_X + 2 * tx] = qh;                 \
            *(float2*)&sab[bs][RR][TILE_X + 2 * tx] =                          \
                make_float2((RL).h1.x * (RL).h2.x, (RL).h1.y * (RL).h2.y);     \
        }                                                                      \
    } while (0)

    for (int ib = 0; ib < NITER; ib += 22) {
#pragma unroll
        for (int jj = 0; jj < 11; ++jj) {
            const int i0 = ib + 2 * jj;
            if (i0 < NITER) {
                PUBLISH(0, R0);
                PUBLISH(1, R1);
                // prefetch next pair (consumed after next sync)
                R0 = load_row(p1, p2, y0 - HALO + i0 + 2, x0, tx);
                R1 = load_row(p1, p2, y0 - HALO + i0 + 3, x0, tx);
                __syncthreads();

                const int s0 = (2 * jj) % 11;       // compile-time
                const int s1 = (2 * jj + 1) % 11;   // compile-time
                HPASS2(s0, 0);
                if (i0 >= 2 * HALO) VPASS2(s0, i0);
                HPASS2(s1, 1);
                if (i0 >= 2 * HALO) VPASS2(s1, i0 + 1);
                bs ^= 1;
                __syncthreads();   // buffer-set reuse guard (2 sets, pair depth)
            }
        }
    }
#undef HPASS2
#undef VPX
#undef VPASS2
#undef PUBLISH
}

// ---------------------------------------------------------------------------
extern "C" void kernel_launch(void* const* d_in, const int* in_sizes, int n_in,
                              void* d_out, int out_size) {
    const float* img1 = (const float*)d_in[0];
    const float* img2 = (const float*)d_in[1];
    float* out = (float*)d_out;
    const int n = in_sizes[0];                 // 32*1*512*512 = 8388608

    minmax_kernel<<<MM_BLOCKS, MM_THREADS>>>((const float4*)img1, n / 4);

    dim3 grid(IMG_W / TILE_X, IMG_H / TILE_Y, n / IMG_N);   // (4, 8, 32)
    ssim_kernel<<<grid, NT>>>(img1, img2, out);
}

// round 7
// speedup vs baseline: 1.2428x; 1.1044x over previous
#include <cuda_runtime.h>

#define IMG_W  512
#define IMG_H  512
#define IMG_N  (IMG_W * IMG_H)
#define TILE_X 64             /* output columns per CTA */
#define NT     32             /* ONE warp; each thread owns 2 adjacent columns */
#define TILE_Y 64
#define HALO   5
#define NITER  (TILE_Y + 2 * HALO)   /* 74 h-conv rows per tile */
#define ROW_E  76             /* smem row entries: cols x0-6 .. x0+69 */
#define MM_BLOCKS 1024
#define MM_THREADS 256

// Normalized 11-tap Gaussian, sigma=1.5, center at ws/2=5.5 (matches ref).
__device__ constexpr float GW[11] = {
    3.2030000e-04f, 2.9556500e-03f, 1.7487670e-02f, 6.6342420e-02f,
    1.6137299e-01f, 2.5168110e-01f, 2.5168110e-01f, 1.6137299e-01f,
    6.6342420e-02f, 1.7487670e-02f, 2.9556500e-03f
};

typedef unsigned long long u64;

__device__ __forceinline__ u64 pack2(float x, float y) {
    u64 r; asm("mov.b64 %0, {%1, %2};" : "=l"(r) : "f"(x), "f"(y)); return r;
}
__device__ __forceinline__ void unpack2(u64 v, float& x, float& y) {
    asm("mov.b64 {%0, %1}, %2;" : "=f"(x), "=f"(y) : "l"(v));
}
__device__ __forceinline__ u64 fma2(u64 a, u64 b, u64 c) {
    u64 d; asm("fma.rn.f32x2 %0, %1, %2, %3;" : "=l"(d) : "l"(a), "l"(b), "l"(c));
    return d;
}
__device__ __forceinline__ u64 mul2(u64 a, u64 b) {
    u64 d; asm("mul.rn.f32x2 %0, %1, %2;" : "=l"(d) : "l"(a), "l"(b));
    return d;
}

// ---------------------------------------------------------------------------
// Global min/max of img1 -> C1, C2 (single kernel, last-block finalize,
// self-resetting counter => graph-replay safe)
// ---------------------------------------------------------------------------
__device__ float g_blk_max[MM_BLOCKS];
__device__ float g_blk_min[MM_BLOCKS];
__device__ unsigned g_arrive = 0;
__device__ float g_C1, g_C2;

__global__ void __launch_bounds__(MM_THREADS)
minmax_kernel(const float4* __restrict__ x, int n4) {
    float mx = -3.402823466e38f, mn = 3.402823466e38f;
    const int stride = gridDim.x * blockDim.x;
    int i = blockIdx.x * blockDim.x + threadIdx.x;
#pragma unroll 8
    for (; i < n4; i += stride) {
        float4 v = x[i];
        mx = fmaxf(mx, fmaxf(fmaxf(v.x, v.y), fmaxf(v.z, v.w)));
        mn = fminf(mn, fminf(fminf(v.x, v.y), fminf(v.z, v.w)));
    }
#pragma unroll
    for (int o = 16; o > 0; o >>= 1) {
        mx = fmaxf(mx, __shfl_xor_sync(0xFFFFFFFFu, mx, o));
        mn = fminf(mn, __shfl_xor_sync(0xFFFFFFFFu, mn, o));
    }
    __shared__ float smx[8], smn[8];
    __shared__ bool last;
    const int w = threadIdx.x >> 5, l = threadIdx.x & 31;
    if (l == 0) { smx[w] = mx; smn[w] = mn; }
    __syncthreads();
    if (threadIdx.x == 0) {
#pragma unroll
        for (int k = 1; k < MM_THREADS / 32; ++k) {
            mx = fmaxf(mx, smx[k]); mn = fminf(mn, smn[k]);
        }
        g_blk_max[blockIdx.x] = mx;
        g_blk_min[blockIdx.x] = mn;
        __threadfence();
        last = (atomicAdd(&g_arrive, 1u) == (unsigned)(gridDim.x - 1));
    }
    __syncthreads();
    if (last) {
        float fx = -3.402823466e38f, fn = 3.402823466e38f;
#pragma unroll
        for (int k = 0; k < MM_BLOCKS / MM_THREADS; ++k) {
            fx = fmaxf(fx, g_blk_max[threadIdx.x + k * MM_THREADS]);
            fn = fminf(fn, g_blk_min[threadIdx.x + k * MM_THREADS]);
        }
#pragma unroll
        for (int o = 16; o > 0; o >>= 1) {
            fx = fmaxf(fx, __shfl_xor_sync(0xFFFFFFFFu, fx, o));
            fn = fminf(fn, __shfl_xor_sync(0xFFFFFFFFu, fn, o));
        }
        if (l == 0) { smx[w] = fx; smn[w] = fn; }
        __syncthreads();
        if (threadIdx.x == 0) {
#pragma unroll
            for (int k = 1; k < MM_THREADS / 32; ++k) {
                fx = fmaxf(fx, smx[k]); fn = fminf(fn, smn[k]);
            }
            float L = fx - fn;
            if (L == 0.f) L = 5.f;
            g_C1 = (0.01f * L) * (0.01f * L);
            g_C2 = (0.03f * L) * (0.03f * L);
            g_arrive = 0;
        }
    }
}

// ---------------------------------------------------------------------------
// Fused separable-SSIM: single-warp CTAs (no block barriers), 2 px/thread,
// tap-window sharing with rolling temps, packed f32x2, pair-batched rows
// ---------------------------------------------------------------------------
struct RowLd { float2 i1, i2, h1, h2; };

__device__ __forceinline__ RowLd load_row(const float* __restrict__ p1,
                                          const float* __restrict__ p2,
                                          int hy, int x0, int tx) {
    RowLd r;
    r.i1 = make_float2(0.f, 0.f); r.i2 = r.i1; r.h1 = r.i1; r.h2 = r.i1;
    if ((unsigned)hy < (unsigned)IMG_H) {
        const int base = hy * IMG_W;
        const int cI = x0 - 6 + 2 * tx;              // even -> aligned float2
        if ((unsigned)cI < (unsigned)IMG_W) {
            r.i1 = *(const float2*)(p1 + base + cI);
            r.i2 = *(const float2*)(p2 + base + cI);
        }
        if (tx < 6) {
            const int cH = cI + TILE_X;              // j = 64 + 2tx
            if ((unsigned)cH < (unsigned)IMG_W) {
                r.h1 = *(const float2*)(p1 + base + cH);
                r.h2 = *(const float2*)(p2 + base + cH);
            }
        }
    }
    return r;
}

__global__ void __launch_bounds__(NT)
ssim_kernel(const float* __restrict__ img1, const float* __restrict__ img2,
            float* __restrict__ out) {
    const int tx = threadIdx.x;
    const int x0 = blockIdx.x * TILE_X;
    const int y0 = blockIdx.y * TILE_Y;
    const long imgoff = (long)blockIdx.z * IMG_N;
    const float* p1 = img1 + imgoff;
    const float* p2 = img2 + imgoff;
    float* po = out + imgoff;

    const float C1 = g_C1;
    const float C2 = g_C2;

    // two alternating buffer-sets, each a PAIR of rows.
    // entry j <-> image col x0-6+j, j = 0..75
    __shared__ u64   spab[2][2][ROW_E];   // (img1, img2) packed
    __shared__ float sab [2][2][ROW_E];   // img1*img2

    u64 WW6[6];
#pragma unroll
    for (int k = 0; k < 6; ++k) WW6[k] = pack2(GW[k], GW[k]);

    // per-pixel vertical rings (2 pixels per thread)
    u64 rm12[2][11], r1122[2][11];
    float r12[2][11];
#pragma unroll
    for (int k = 0; k < 11; ++k) {
        rm12[0][k] = 0ull; rm12[1][k] = 0ull;
        r1122[0][k] = 0ull; r1122[1][k] = 0ull;
        r12[0][k] = 0.f; r12[1][k] = 0.f;
    }

    RowLd R0 = load_row(p1, p2, y0 - HALO,     x0, tx);
    RowLd R1 = load_row(p1, p2, y0 - HALO + 1, x0, tx);
    int bs = 0;

    // h-pass for BOTH pixels, rolling 2-deep tap window (low live regs).
    // taps: px0 at j = 2tx+1..2tx+11, px1 at 2tx+2..2tx+12.
#define HPASS2(SLOT, RR)                                                       \
    do {                                                                       \
        const int jb = 2 * tx + 1;                                             \
        u64 hA01 = 0ull, hA23 = 0ull, hB01 = 0ull, hB23 = 0ull;                \
        float hA4 = 0.f, hB4 = 0.f;                                            \
        u64   pP  = spab[bs][RR][jb];                                          \
        u64   ppP = mul2(pP, pP);                                              \
        float abP = sab[bs][RR][jb];                                           \
        _Pragma("unroll")                                                      \
        for (int k = 0; k < 11; ++k) {                                         \
            const int kk = (k <= 5) ? k : (11 - k);                            \
            const u64   pC  = spab[bs][RR][jb + k + 1];                        \
            const u64   ppC = mul2(pC, pC);                                    \
            const float abC = sab[bs][RR][jb + k + 1];                         \
            hA01 = fma2(pP,  WW6[kk], hA01);                                   \
            hA23 = fma2(ppP, WW6[kk], hA23);                                   \
            hA4  = fmaf(abP, GW[k],   hA4);                                    \
            hB01 = fma2(pC,  WW6[kk], hB01);                                   \
            hB23 = fma2(ppC, WW6[kk], hB23);                                   \
            hB4  = fmaf(abC, GW[k],   hB4);                                    \
            pP = pC; ppP = ppC; abP = abC;                                     \
        }                                                                      \
        rm12[0][SLOT] = hA01; r1122[0][SLOT] = hA23; r12[0][SLOT] = hA4;       \
        rm12[1][SLOT] = hB01; r1122[1][SLOT] = hB23; r12[1][SLOT] = hB4;       \
    } while (0)

#define VPX(PX, SLOT, RES)                                                     \
    do {                                                                       \
        u64 M = 0ull, S = 0ull; float s12 = 0.f;                               \
        _Pragma("unroll")                                                      \
        for (int k = 0; k < 11; ++k) {                                         \
            const int s  = ((SLOT) + 1 + k) % 11;                              \
            const int kk = (k <= 5) ? k : (11 - k);                            \
            M   = fma2(rm12[PX][s],  WW6[kk], M);                              \
            S   = fma2(r1122[PX][s], WW6[kk], S);                              \
            s12 = fmaf(r12[PX][s], GW[k], s12);                                \
        }                                                                      \
        float mu1, mu2, e11, e22;                                              \
        unpack2(M, mu1, mu2); unpack2(S, e11, e22);                            \
        const float mu1sq = mu1 * mu1;                                         \
        const float mu2sq = mu2 * mu2;                                         \
        const float mu12  = mu1 * mu2;                                         \
        const float num = fmaf(2.f, mu12, C1) * fmaf(2.f, s12 - mu12, C2);     \
        const float den = (mu1sq + mu2sq + C1) *                               \
                          ((e11 - mu1sq) + (e22 - mu2sq) + C2);                \
        RES = __fdividef(num, den);                                            \
    } while (0)

#define VPASS2(SLOT, ROW)                                                      \
    do {                                                                       \
        float2 res;                                                            \
        VPX(0, SLOT, res.x);                                                   \
        VPX(1, SLOT, res.y);                                                   \
        *(float2*)(po + (y0 + (ROW) - 2 * HALO) * IMG_W + x0 + 2 * tx) = res;  \
    } while (0)

#define PUBLISH(RR, RL)                                                        \
    do {                                                                       \
        ulonglong2 q;                                                          \
        q.x = pack2((RL).i1.x, (RL).i2.x);                                     \
        q.y = pack2((RL).i1.y, (RL).i2.y);                                     \
        *(ulonglong2*)&spab[bs][RR][2 * tx] = q;                               \
        *(float2*)&sab[bs][RR][2 * tx] =                                       \
            make_float2((RL).i1.x * (RL).i2.x, (RL).i1.y * (RL).i2.y);         \
        if (tx < 6) {                                                          \
            ulonglong2 qh;                                                     \
            qh.x = pack2((RL).h1.x, (RL).h2.x);                                \
            qh.y = pack2((RL).h1.y, (RL).h2.y);                                \
            *(ulonglong2*)&spab[bs][RR][TILE_X + 2 * tx] = qh;                 \
            *(float2*)&sab[bs][RR][TILE_X + 2 * tx] =                          \
                make_float2((RL).h1.x * (RL).h2.x, (RL).h1.y * (RL).h2.y);     \
        }                                                                      \
    } while (0)

    for (int ib = 0; ib < NITER; ib += 22) {
#pragma unroll
        for (int jj = 0; jj < 11; ++jj) {
            const int i0 = ib + 2 * jj;
            if (i0 < NITER) {
                PUBLISH(0, R0);
                PUBLISH(1, R1);
                // prefetch next pair (consumed after next sync)
                R0 = load_row(p1, p2, y0 - HALO + i0 + 2, x0, tx);
                R1 = load_row(p1, p2, y0 - HALO + i0 + 3, x0, tx);
                __syncwarp();    // single warp: publish -> consume handshake

                const int s0 = (2 * jj) % 11;       // compile-time
                const int s1 = (2 * jj + 1) % 11;   // compile-time
                HPASS2(s0, 0);
                if (i0 >= 2 * HALO) VPASS2(s0, i0);
                HPASS2(s1, 1);
                if (i0 >= 2 * HALO) VPASS2(s1, i0 + 1);
                bs ^= 1;
                // republish of this buffer set is ordered behind the NEXT
                // iteration's __syncwarp -> one sync per iteration suffices
            }
        }
    }
#undef HPASS2
#undef VPX
#undef VPASS2
#undef PUBLISH
}

// ---------------------------------------------------------------------------
extern "C" void kernel_launch(void* const* d_in, const int* in_sizes, int n_in,
                              void* d_out, int out_size) {
    const float* img1 = (const float*)d_in[0];
    const float* img2 = (const float*)d_in[1];
    float* out = (float*)d_out;
    const int n = in_sizes[0];                 // 32*1*512*512 = 8388608

    minmax_kernel<<<MM_BLOCKS, MM_THREADS>>>((const float4*)img1, n / 4);

    dim3 grid(IMG_W / TILE_X, IMG_H / TILE_Y, n / IMG_N);   // (8, 8, 32)
    ssim_kernel<<<grid, NT>>>(img1, img2, out);
}